// round 1
// baseline (speedup 1.0000x reference)
#include <cuda_runtime.h>
#include <cuda_bf16.h>

#define HIDDEN 512
#define MAX_LEN 4096
#define BATCH 32

// Scratch: v[b][h] = sum_o hidden[b][o] * W[o][h]   (Wᵀ·hidden per batch)
__device__ float4 g_v4[BATCH * (HIDDEN / 4)];  // 64 KB

// ---------------------------------------------------------------------------
// Kernel 1: v[b] = hiddenᵀ[b] @ W.   Grid: 32 blocks (one per batch), 512 thr.
// Block split: 4 o-groups x 128 h-threads; each thread owns 4 h columns
// (float4 loads of W rows), partials reduced through smem.
// ---------------------------------------------------------------------------
__global__ void v_kernel(const float* __restrict__ hidden,
                         const float* __restrict__ W) {
    __shared__ float hs[HIDDEN];
    __shared__ float4 part[3][128];

    const int b = blockIdx.x;
    const int t = threadIdx.x;

    hs[t] = hidden[b * HIDDEN + t];
    __syncthreads();

    const int g = t >> 7;       // o-group 0..3
    const int j = t & 127;      // h-quad index 0..127
    const float4* __restrict__ W4 = reinterpret_cast<const float4*>(W);

    float4 acc = make_float4(0.f, 0.f, 0.f, 0.f);
    const int o0 = g * 128;
#pragma unroll 8
    for (int o = 0; o < 128; o++) {
        const float hv = hs[o0 + o];
        const float4 w = W4[(size_t)(o0 + o) * 128 + j];
        acc.x += hv * w.x;
        acc.y += hv * w.y;
        acc.z += hv * w.z;
        acc.w += hv * w.w;
    }

    if (g > 0) part[g - 1][j] = acc;
    __syncthreads();
    if (g == 0) {
#pragma unroll
        for (int k = 0; k < 3; k++) {
            const float4 p = part[k][j];
            acc.x += p.x; acc.y += p.y; acc.z += p.z; acc.w += p.w;
        }
        g_v4[b * 128 + j] = acc;
    }
}

// ---------------------------------------------------------------------------
// Kernel 2: energies[b][l] = v[b] . enc[l][b]  (bias term dropped: constant in
// l, softmax shift-invariant). One warp per (l,b) row; 8 warps/block.
// Rows are r = l*32 + b, so a block reads 16 KB of contiguous DRAM.
// ---------------------------------------------------------------------------
__global__ void energy_kernel(const float* __restrict__ enc,
                              float* __restrict__ out) {
    const int r    = blockIdx.x * 8 + (threadIdx.x >> 5);
    const int lane = threadIdx.x & 31;
    const int b    = r & (BATCH - 1);
    const int l    = r >> 5;

    const float4* __restrict__ e4 =
        reinterpret_cast<const float4*>(enc) + (size_t)r * (HIDDEN / 4);
    const float4* __restrict__ v4 = g_v4 + b * (HIDDEN / 4);

    float acc = 0.f;
#pragma unroll
    for (int k = 0; k < 4; k++) {
        const float4 a = e4[lane + k * 32];
        const float4 w = __ldg(&v4[lane + k * 32]);
        acc += a.x * w.x + a.y * w.y + a.z * w.z + a.w * w.w;
    }
#pragma unroll
    for (int off = 16; off; off >>= 1)
        acc += __shfl_xor_sync(0xFFFFFFFFu, acc, off);

    if (lane == 0) out[(size_t)b * MAX_LEN + l] = acc;
}

// ---------------------------------------------------------------------------
// Kernel 3: in-place softmax over each row of out[32][4096].
// 32 blocks x 1024 threads; each thread holds one float4 of the row.
// ---------------------------------------------------------------------------
__global__ void softmax_kernel(float* __restrict__ out) {
    __shared__ float red[32];

    const int b = blockIdx.x;
    const int t = threadIdx.x;
    float4* __restrict__ row4 =
        reinterpret_cast<float4*>(out) + (size_t)b * (MAX_LEN / 4);

    float4 x = row4[t];

    // --- max reduce ---
    float m = fmaxf(fmaxf(x.x, x.y), fmaxf(x.z, x.w));
#pragma unroll
    for (int o = 16; o; o >>= 1)
        m = fmaxf(m, __shfl_xor_sync(0xFFFFFFFFu, m, o));
    if ((t & 31) == 0) red[t >> 5] = m;
    __syncthreads();
    if (t < 32) {
        float mm = red[t];
#pragma unroll
        for (int o = 16; o; o >>= 1)
            mm = fmaxf(mm, __shfl_xor_sync(0xFFFFFFFFu, mm, o));
        if (t == 0) red[0] = mm;
    }
    __syncthreads();
    m = red[0];
    __syncthreads();   // protect red before reuse for sum

    // --- exp + sum reduce ---
    x.x = __expf(x.x - m);
    x.y = __expf(x.y - m);
    x.z = __expf(x.z - m);
    x.w = __expf(x.w - m);
    float s = x.x + x.y + x.z + x.w;
#pragma unroll
    for (int o = 16; o; o >>= 1)
        s += __shfl_xor_sync(0xFFFFFFFFu, s, o);
    if ((t & 31) == 0) red[t >> 5] = s;
    __syncthreads();
    if (t < 32) {
        float ss = red[t];
#pragma unroll
        for (int o = 16; o; o >>= 1)
            ss += __shfl_xor_sync(0xFFFFFFFFu, ss, o);
        if (t == 0) red[0] = ss;
    }
    __syncthreads();
    const float inv = 1.0f / red[0];

    x.x *= inv; x.y *= inv; x.z *= inv; x.w *= inv;
    row4[t] = x;
}

// ---------------------------------------------------------------------------
extern "C" void kernel_launch(void* const* d_in, const int* in_sizes, int n_in,
                              void* d_out, int out_size) {
    const float* hidden = (const float*)d_in[0];   // [1, 32, 512]
    const float* enc    = (const float*)d_in[1];   // [4096, 32, 512]
    const float* W      = (const float*)d_in[2];   // [512, 512]
    // d_in[3] = bias: provably irrelevant (constant shift under softmax)
    float* out = (float*)d_out;                    // [32, 1, 4096]

    v_kernel<<<BATCH, HIDDEN>>>(hidden, W);

    const int rows = MAX_LEN * BATCH;              // 131072
    energy_kernel<<<rows / 8, 256>>>(enc, out);

    softmax_kernel<<<BATCH, MAX_LEN / 4>>>(out);
}

// round 2
// speedup vs baseline: 1.3168x; 1.3168x over previous
#include <cuda_runtime.h>
#include <cuda_bf16.h>

#define HIDDEN 512
#define MAX_LEN 4096
#define BATCH 32

// Scratch: v[b][h] = sum_o hidden[b][o] * W[o][h]   (Wᵀ·hidden per batch)
__device__ float4 g_v4[BATCH * (HIDDEN / 4)];  // 64 KB

// ---------------------------------------------------------------------------
// Kernel 1: v[b] = hiddenᵀ[b] @ W.
// Grid: (BATCH, 8) = 256 blocks, 256 threads = 16 o-groups x 16 h-quads.
// Block (b, hc) computes v[b][hc*64 .. hc*64+63] (16 float4 outputs).
// Each thread accumulates 32 o-rows of a W panel; 16 partials per h-quad are
// tree-reduced in smem. W panel reads are 256B-contiguous per half-warp.
// ---------------------------------------------------------------------------
__global__ void v_kernel(const float* __restrict__ hidden,
                         const float* __restrict__ W) {
    __shared__ float hs[HIDDEN];
    __shared__ float4 part[16][16];   // [o-group][h-quad]

    const int b  = blockIdx.x;
    const int hc = blockIdx.y;        // h-chunk 0..7
    const int t  = threadIdx.x;       // 0..255

    hs[t]       = hidden[b * HIDDEN + t];
    hs[t + 256] = hidden[b * HIDDEN + t + 256];
    __syncthreads();

    const int g  = t >> 4;            // o-group 0..15 (32 o-rows each)
    const int j  = t & 15;            // local h-quad 0..15
    const int jq = hc * 16 + j;       // global h-quad 0..127

    const float4* __restrict__ W4 = reinterpret_cast<const float4*>(W);

    float4 acc = make_float4(0.f, 0.f, 0.f, 0.f);
    const int o0 = g * 32;
#pragma unroll
    for (int o = 0; o < 32; o++) {
        const float  hv = hs[o0 + o];
        const float4 w  = W4[(size_t)(o0 + o) * 128 + jq];
        acc.x += hv * w.x;
        acc.y += hv * w.y;
        acc.z += hv * w.z;
        acc.w += hv * w.w;
    }
    part[g][j] = acc;
    __syncthreads();

#pragma unroll
    for (int s = 8; s; s >>= 1) {
        if (g < s) {
            const float4 p = part[g + s][j];
            float4 a = part[g][j];
            a.x += p.x; a.y += p.y; a.z += p.z; a.w += p.w;
            part[g][j] = a;
        }
        __syncthreads();
    }

    if (t < 16) g_v4[b * 128 + jq] = part[0][t];
}

// ---------------------------------------------------------------------------
// Kernel 2: energies[b][l] = v[b] . enc[l][b]  (bias term dropped: constant in
// l, softmax shift-invariant). One warp per (l,b) row; 8 warps/block.
// Rows are r = l*32 + b, so a block reads 16 KB of contiguous DRAM.
// ---------------------------------------------------------------------------
__global__ void energy_kernel(const float* __restrict__ enc,
                              float* __restrict__ out) {
    const int r    = blockIdx.x * 8 + (threadIdx.x >> 5);
    const int lane = threadIdx.x & 31;
    const int b    = r & (BATCH - 1);
    const int l    = r >> 5;

    const float4* __restrict__ e4 =
        reinterpret_cast<const float4*>(enc) + (size_t)r * (HIDDEN / 4);
    const float4* __restrict__ v4 = g_v4 + b * (HIDDEN / 4);

    float acc = 0.f;
#pragma unroll
    for (int k = 0; k < 4; k++) {
        const float4 a = e4[lane + k * 32];
        const float4 w = __ldg(&v4[lane + k * 32]);
        acc += a.x * w.x + a.y * w.y + a.z * w.z + a.w * w.w;
    }
#pragma unroll
    for (int off = 16; off; off >>= 1)
        acc += __shfl_xor_sync(0xFFFFFFFFu, acc, off);

    if (lane == 0) out[(size_t)b * MAX_LEN + l] = acc;
}

// ---------------------------------------------------------------------------
// Kernel 3: in-place softmax over each row of out[32][4096].
// 32 blocks x 1024 threads; each thread holds one float4 of the row.
// ---------------------------------------------------------------------------
__global__ void softmax_kernel(float* __restrict__ out) {
    __shared__ float red[32];

    const int b = blockIdx.x;
    const int t = threadIdx.x;
    float4* __restrict__ row4 =
        reinterpret_cast<float4*>(out) + (size_t)b * (MAX_LEN / 4);

    float4 x = row4[t];

    // --- max reduce ---
    float m = fmaxf(fmaxf(x.x, x.y), fmaxf(x.z, x.w));
#pragma unroll
    for (int o = 16; o; o >>= 1)
        m = fmaxf(m, __shfl_xor_sync(0xFFFFFFFFu, m, o));
    if ((t & 31) == 0) red[t >> 5] = m;
    __syncthreads();
    if (t < 32) {
        float mm = red[t];
#pragma unroll
        for (int o = 16; o; o >>= 1)
            mm = fmaxf(mm, __shfl_xor_sync(0xFFFFFFFFu, mm, o));
        if (t == 0) red[0] = mm;
    }
    __syncthreads();
    m = red[0];
    __syncthreads();   // protect red before reuse for sum

    // --- exp + sum reduce ---
    x.x = __expf(x.x - m);
    x.y = __expf(x.y - m);
    x.z = __expf(x.z - m);
    x.w = __expf(x.w - m);
    float s = x.x + x.y + x.z + x.w;
#pragma unroll
    for (int o = 16; o; o >>= 1)
        s += __shfl_xor_sync(0xFFFFFFFFu, s, o);
    if ((t & 31) == 0) red[t >> 5] = s;
    __syncthreads();
    if (t < 32) {
        float ss = red[t];
#pragma unroll
        for (int o = 16; o; o >>= 1)
            ss += __shfl_xor_sync(0xFFFFFFFFu, ss, o);
        if (t == 0) red[0] = ss;
    }
    __syncthreads();
    const float inv = 1.0f / red[0];

    x.x *= inv; x.y *= inv; x.z *= inv; x.w *= inv;
    row4[t] = x;
}

// ---------------------------------------------------------------------------
extern "C" void kernel_launch(void* const* d_in, const int* in_sizes, int n_in,
                              void* d_out, int out_size) {
    const float* hidden = (const float*)d_in[0];   // [1, 32, 512]
    const float* enc    = (const float*)d_in[1];   // [4096, 32, 512]
    const float* W      = (const float*)d_in[2];   // [512, 512]
    // d_in[3] = bias: provably irrelevant (constant shift under softmax)
    float* out = (float*)d_out;                    // [32, 1, 4096]

    dim3 vgrid(BATCH, 8);
    v_kernel<<<vgrid, 256>>>(hidden, W);

    const int rows = MAX_LEN * BATCH;              // 131072
    energy_kernel<<<rows / 8, 256>>>(enc, out);

    softmax_kernel<<<BATCH, MAX_LEN / 4>>>(out);
}

// round 3
// speedup vs baseline: 1.3711x; 1.0412x over previous
#include <cuda_runtime.h>
#include <cuda_bf16.h>

#define HIDDEN 512
#define MAX_LEN 4096
#define BATCH 32

// Scratch: v[b][h] = sum_o hidden[b][o] * W[o][h]   (Wᵀ·hidden per batch)
__device__ float4 g_v4[BATCH * (HIDDEN / 4)];  // 64 KB

// ---------------------------------------------------------------------------
// Kernel 1: v[b] = hiddenᵀ[b] @ W.
// Grid: (8 batch-groups, 16 h-chunks) = 128 blocks (one wave), 256 threads =
// 32 o-groups x 8 h-quads. Each block computes 4 batches x 32 h-columns, so
// every W float4 loaded is reused by 4 FMA chains in registers: L2 traffic
// drops to 8 MB (vs 32 MB), DRAM stays 1 MB. Reduction: 2 shfl rounds fold
// 4 o-groups/warp, then one smem pass folds the 8 warps.
// ---------------------------------------------------------------------------
__global__ void v_kernel(const float* __restrict__ hidden,
                         const float* __restrict__ W) {
    __shared__ float  hs[4][HIDDEN];      // 4 batches of hidden
    __shared__ float4 part[4][8][8];      // [batch][warp][h-quad]

    const int bg = blockIdx.x;            // batch group: batches bg*4..bg*4+3
    const int hc = blockIdx.y;            // h-chunk: quads hc*8..hc*8+7
    const int t  = threadIdx.x;           // 0..255

    const float* __restrict__ hsrc = hidden + bg * 4 * HIDDEN;
#pragma unroll
    for (int i = t; i < 4 * HIDDEN; i += 256)
        hs[i >> 9][i & (HIDDEN - 1)] = hsrc[i];
    __syncthreads();

    const int og = t >> 3;                // o-group 0..31 (16 rows each)
    const int j  = t & 7;                 // local h-quad 0..7
    const int jq = hc * 8 + j;            // global h-quad 0..127

    const float4* __restrict__ W4 = reinterpret_cast<const float4*>(W);

    float4 acc[4];
#pragma unroll
    for (int bi = 0; bi < 4; bi++) acc[bi] = make_float4(0.f, 0.f, 0.f, 0.f);

    const int o0 = og * 16;
#pragma unroll
    for (int o = 0; o < 16; o++) {
        const float4 w = W4[(size_t)(o0 + o) * 128 + jq];
#pragma unroll
        for (int bi = 0; bi < 4; bi++) {
            const float hv = hs[bi][o0 + o];
            acc[bi].x += hv * w.x;
            acc[bi].y += hv * w.y;
            acc[bi].z += hv * w.z;
            acc[bi].w += hv * w.w;
        }
    }

    // Warp holds 4 o-groups (lane>>3) x 8 quads (lane&7): fold o-groups.
#pragma unroll
    for (int off = 8; off <= 16; off <<= 1) {
#pragma unroll
        for (int bi = 0; bi < 4; bi++) {
            acc[bi].x += __shfl_xor_sync(0xFFFFFFFFu, acc[bi].x, off);
            acc[bi].y += __shfl_xor_sync(0xFFFFFFFFu, acc[bi].y, off);
            acc[bi].z += __shfl_xor_sync(0xFFFFFFFFu, acc[bi].z, off);
            acc[bi].w += __shfl_xor_sync(0xFFFFFFFFu, acc[bi].w, off);
        }
    }

    const int lane = t & 31;
    const int warp = t >> 5;
    if (lane < 8) {
#pragma unroll
        for (int bi = 0; bi < 4; bi++) part[bi][warp][lane] = acc[bi];
    }
    __syncthreads();

    // Fold the 8 warps: 32 threads, one (batch, quad) pair each.
    if (t < 32) {
        const int bi = t >> 3;
        const int jj = t & 7;
        float4 s = part[bi][0][jj];
#pragma unroll
        for (int w = 1; w < 8; w++) {
            const float4 p = part[bi][w][jj];
            s.x += p.x; s.y += p.y; s.z += p.z; s.w += p.w;
        }
        g_v4[(bg * 4 + bi) * 128 + hc * 8 + jj] = s;
    }
}

// ---------------------------------------------------------------------------
// Kernel 2: energies[b][l] = v[b] . enc[l][b]  (bias term dropped: constant in
// l, softmax shift-invariant). One warp per (l,b) row; 8 warps/block.
// Rows are r = l*32 + b, so a block reads 16 KB of contiguous DRAM.
// ---------------------------------------------------------------------------
__global__ void energy_kernel(const float* __restrict__ enc,
                              float* __restrict__ out) {
    const int r    = blockIdx.x * 8 + (threadIdx.x >> 5);
    const int lane = threadIdx.x & 31;
    const int b    = r & (BATCH - 1);
    const int l    = r >> 5;

    const float4* __restrict__ e4 =
        reinterpret_cast<const float4*>(enc) + (size_t)r * (HIDDEN / 4);
    const float4* __restrict__ v4 = g_v4 + b * (HIDDEN / 4);

    float acc = 0.f;
#pragma unroll
    for (int k = 0; k < 4; k++) {
        const float4 a = e4[lane + k * 32];
        const float4 w = __ldg(&v4[lane + k * 32]);
        acc += a.x * w.x + a.y * w.y + a.z * w.z + a.w * w.w;
    }
#pragma unroll
    for (int off = 16; off; off >>= 1)
        acc += __shfl_xor_sync(0xFFFFFFFFu, acc, off);

    if (lane == 0) out[(size_t)b * MAX_LEN + l] = acc;
}

// ---------------------------------------------------------------------------
// Kernel 3: in-place softmax over each row of out[32][4096].
// 32 blocks x 1024 threads; each thread holds one float4 of the row.
// ---------------------------------------------------------------------------
__global__ void softmax_kernel(float* __restrict__ out) {
    __shared__ float red[32];

    const int b = blockIdx.x;
    const int t = threadIdx.x;
    float4* __restrict__ row4 =
        reinterpret_cast<float4*>(out) + (size_t)b * (MAX_LEN / 4);

    float4 x = row4[t];

    // --- max reduce ---
    float m = fmaxf(fmaxf(x.x, x.y), fmaxf(x.z, x.w));
#pragma unroll
    for (int o = 16; o; o >>= 1)
        m = fmaxf(m, __shfl_xor_sync(0xFFFFFFFFu, m, o));
    if ((t & 31) == 0) red[t >> 5] = m;
    __syncthreads();
    if (t < 32) {
        float mm = red[t];
#pragma unroll
        for (int o = 16; o; o >>= 1)
            mm = fmaxf(mm, __shfl_xor_sync(0xFFFFFFFFu, mm, o));
        if (t == 0) red[0] = mm;
    }
    __syncthreads();
    m = red[0];
    __syncthreads();   // protect red before reuse for sum

    // --- exp + sum reduce ---
    x.x = __expf(x.x - m);
    x.y = __expf(x.y - m);
    x.z = __expf(x.z - m);
    x.w = __expf(x.w - m);
    float s = x.x + x.y + x.z + x.w;
#pragma unroll
    for (int o = 16; o; o >>= 1)
        s += __shfl_xor_sync(0xFFFFFFFFu, s, o);
    if ((t & 31) == 0) red[t >> 5] = s;
    __syncthreads();
    if (t < 32) {
        float ss = red[t];
#pragma unroll
        for (int o = 16; o; o >>= 1)
            ss += __shfl_xor_sync(0xFFFFFFFFu, ss, o);
        if (t == 0) red[0] = ss;
    }
    __syncthreads();
    const float inv = 1.0f / red[0];

    x.x *= inv; x.y *= inv; x.z *= inv; x.w *= inv;
    row4[t] = x;
}

// ---------------------------------------------------------------------------
extern "C" void kernel_launch(void* const* d_in, const int* in_sizes, int n_in,
                              void* d_out, int out_size) {
    const float* hidden = (const float*)d_in[0];   // [1, 32, 512]
    const float* enc    = (const float*)d_in[1];   // [4096, 32, 512]
    const float* W      = (const float*)d_in[2];   // [512, 512]
    // d_in[3] = bias: provably irrelevant (constant shift under softmax)
    float* out = (float*)d_out;                    // [32, 1, 4096]

    dim3 vgrid(8, 16);
    v_kernel<<<vgrid, 256>>>(hidden, W);

    const int rows = MAX_LEN * BATCH;              // 131072
    energy_kernel<<<rows / 8, 256>>>(enc, out);

    softmax_kernel<<<BATCH, MAX_LEN / 4>>>(out);
}

// round 4
// speedup vs baseline: 1.4244x; 1.0388x over previous
#include <cuda_runtime.h>
#include <cuda_bf16.h>

#define HIDDEN 512
#define MAX_LEN 4096
#define BATCH 32

// Scratch: v[b][h] = sum_o hidden[b][o] * W[o][h]   (Wᵀ·hidden per batch)
__device__ float4 g_v4[BATCH * (HIDDEN / 4)];  // 64 KB

// ---------------------------------------------------------------------------
// Kernel 1: v[b] = hiddenᵀ[b] @ W.
// Grid: (8 batch-groups, 16 h-chunks) = 128 blocks, 512 threads =
// 64 o-groups x 8 h-quads. Each thread: 8 front-batched float4 W loads
// (full MLP), reused across 4 batches in registers. Reduction: 2 shfl
// rounds fold 4 o-groups per warp, then a 16-warp smem fold.
// ---------------------------------------------------------------------------
__global__ void v_kernel(const float* __restrict__ hidden,
                         const float* __restrict__ W) {
    __shared__ float  hs[4][HIDDEN];      // 4 batches of hidden
    __shared__ float4 part[4][16][8];     // [batch][warp][h-quad]

    const int bg = blockIdx.x;            // batch group: batches bg*4..bg*4+3
    const int hc = blockIdx.y;            // h-chunk: quads hc*8..hc*8+7
    const int t  = threadIdx.x;           // 0..511

    // 4*512 floats = 512 float4s: one per thread.
    reinterpret_cast<float4*>(&hs[0][0])[t] =
        reinterpret_cast<const float4*>(hidden + bg * 4 * HIDDEN)[t];
    __syncthreads();

    const int og = t >> 3;                // o-group 0..63 (8 rows each)
    const int j  = t & 7;                 // local h-quad 0..7
    const int jq = hc * 8 + j;            // global h-quad 0..127

    const float4* __restrict__ W4 = reinterpret_cast<const float4*>(W);

    // Front-batch all 8 W loads (independent of acc chains).
    float4 w[8];
    const int o0 = og * 8;
#pragma unroll
    for (int o = 0; o < 8; o++)
        w[o] = W4[(size_t)(o0 + o) * 128 + jq];

    float4 acc[4];
#pragma unroll
    for (int bi = 0; bi < 4; bi++) acc[bi] = make_float4(0.f, 0.f, 0.f, 0.f);

#pragma unroll
    for (int o = 0; o < 8; o++) {
#pragma unroll
        for (int bi = 0; bi < 4; bi++) {
            const float hv = hs[bi][o0 + o];
            acc[bi].x += hv * w[o].x;
            acc[bi].y += hv * w[o].y;
            acc[bi].z += hv * w[o].z;
            acc[bi].w += hv * w[o].w;
        }
    }

    // Warp holds 4 o-groups (lane>>3) x 8 quads (lane&7): fold o-groups.
#pragma unroll
    for (int off = 8; off <= 16; off <<= 1) {
#pragma unroll
        for (int bi = 0; bi < 4; bi++) {
            acc[bi].x += __shfl_xor_sync(0xFFFFFFFFu, acc[bi].x, off);
            acc[bi].y += __shfl_xor_sync(0xFFFFFFFFu, acc[bi].y, off);
            acc[bi].z += __shfl_xor_sync(0xFFFFFFFFu, acc[bi].z, off);
            acc[bi].w += __shfl_xor_sync(0xFFFFFFFFu, acc[bi].w, off);
        }
    }

    const int lane = t & 31;
    const int warp = t >> 5;
    if (lane < 8) {
#pragma unroll
        for (int bi = 0; bi < 4; bi++) part[bi][warp][lane] = acc[bi];
    }
    __syncthreads();

    // Fold the 16 warps: 32 threads, one (batch, quad) pair each.
    if (t < 32) {
        const int bi = t >> 3;
        const int jj = t & 7;
        float4 s = part[bi][0][jj];
#pragma unroll
        for (int wi = 1; wi < 16; wi++) {
            const float4 p = part[bi][wi][jj];
            s.x += p.x; s.y += p.y; s.z += p.z; s.w += p.w;
        }
        g_v4[(bg * 4 + bi) * 128 + hc * 8 + jj] = s;
    }
}

// ---------------------------------------------------------------------------
// Kernel 2: energies[b][l] = v[b] . enc[l][b]  (bias term dropped: constant in
// l, softmax shift-invariant). One warp per (l,b) row; 8 warps/block.
// Rows are r = l*32 + b, so a block reads 16 KB of contiguous DRAM.
// enc is a zero-reuse stream -> __ldcs (evict-first).
// ---------------------------------------------------------------------------
__global__ void energy_kernel(const float* __restrict__ enc,
                              float* __restrict__ out) {
    const int r    = blockIdx.x * 8 + (threadIdx.x >> 5);
    const int lane = threadIdx.x & 31;
    const int b    = r & (BATCH - 1);
    const int l    = r >> 5;

    const float4* __restrict__ e4 =
        reinterpret_cast<const float4*>(enc) + (size_t)r * (HIDDEN / 4);
    const float4* __restrict__ v4 = g_v4 + b * (HIDDEN / 4);

    float acc = 0.f;
#pragma unroll
    for (int k = 0; k < 4; k++) {
        const float4 a = __ldcs(&e4[lane + k * 32]);
        const float4 w = __ldg(&v4[lane + k * 32]);
        acc += a.x * w.x + a.y * w.y + a.z * w.z + a.w * w.w;
    }
#pragma unroll
    for (int off = 16; off; off >>= 1)
        acc += __shfl_xor_sync(0xFFFFFFFFu, acc, off);

    if (lane == 0) out[(size_t)b * MAX_LEN + l] = acc;
}

// ---------------------------------------------------------------------------
// Kernel 3: in-place softmax over each row of out[32][4096].
// 32 blocks x 1024 threads; each thread holds one float4 of the row.
// ---------------------------------------------------------------------------
__global__ void softmax_kernel(float* __restrict__ out) {
    __shared__ float red[32];

    const int b = blockIdx.x;
    const int t = threadIdx.x;
    float4* __restrict__ row4 =
        reinterpret_cast<float4*>(out) + (size_t)b * (MAX_LEN / 4);

    float4 x = row4[t];

    // --- max reduce ---
    float m = fmaxf(fmaxf(x.x, x.y), fmaxf(x.z, x.w));
#pragma unroll
    for (int o = 16; o; o >>= 1)
        m = fmaxf(m, __shfl_xor_sync(0xFFFFFFFFu, m, o));
    if ((t & 31) == 0) red[t >> 5] = m;
    __syncthreads();
    if (t < 32) {
        float mm = red[t];
#pragma unroll
        for (int o = 16; o; o >>= 1)
            mm = fmaxf(mm, __shfl_xor_sync(0xFFFFFFFFu, mm, o));
        if (t == 0) red[0] = mm;
    }
    __syncthreads();
    m = red[0];
    __syncthreads();   // protect red before reuse for sum

    // --- exp + sum reduce ---
    x.x = __expf(x.x - m);
    x.y = __expf(x.y - m);
    x.z = __expf(x.z - m);
    x.w = __expf(x.w - m);
    float s = x.x + x.y + x.z + x.w;
#pragma unroll
    for (int o = 16; o; o >>= 1)
        s += __shfl_xor_sync(0xFFFFFFFFu, s, o);
    if ((t & 31) == 0) red[t >> 5] = s;
    __syncthreads();
    if (t < 32) {
        float ss = red[t];
#pragma unroll
        for (int o = 16; o; o >>= 1)
            ss += __shfl_xor_sync(0xFFFFFFFFu, ss, o);
        if (t == 0) red[0] = ss;
    }
    __syncthreads();
    const float inv = 1.0f / red[0];

    x.x *= inv; x.y *= inv; x.z *= inv; x.w *= inv;
    row4[t] = x;
}

// ---------------------------------------------------------------------------
extern "C" void kernel_launch(void* const* d_in, const int* in_sizes, int n_in,
                              void* d_out, int out_size) {
    const float* hidden = (const float*)d_in[0];   // [1, 32, 512]
    const float* enc    = (const float*)d_in[1];   // [4096, 32, 512]
    const float* W      = (const float*)d_in[2];   // [512, 512]
    // d_in[3] = bias: provably irrelevant (constant shift under softmax)
    float* out = (float*)d_out;                    // [32, 1, 4096]

    dim3 vgrid(8, 16);
    v_kernel<<<vgrid, 512>>>(hidden, W);

    const int rows = MAX_LEN * BATCH;              // 131072
    energy_kernel<<<rows / 8, 256>>>(enc, out);

    softmax_kernel<<<BATCH, MAX_LEN / 4>>>(out);
}